// round 15
// baseline (speedup 1.0000x reference)
#include <cuda_runtime.h>
#include <cuda_fp16.h>
#include <cstdint>

// out[i,j,o] = sum_h x[i+1,h]*x[j+1,h]*W[o,h] + b[o]
// (diff/W2 term is antisymmetric -> cancels under (P+P^T)/2 symmetrization)
//
// D_o = A_o B^T, A_o = X .* w_o, B = X (512x768 f32)
// Single fp16 MMA per k16 (measured rel_err 2.9e-4 < 1e-3).
// prep: 3 fp16 images (A0h=x*w0, A1h=x*w1, Bh=x) + zero out.
// main: grid (136 tri-tiles, 2 K-splits) = 272 CTAs, each K=384 resident
// in smem (73.5 KB -> 3 CTAs/SM), barrier-free LDSM+HMMA (4 groups x 4
// warps), in-CTA combine, then exactly 2 commutative red.global.add per
// output element (deterministic: a+b == b+a).

#define HDIM 768
#define KH 384                     // K per CTA (half)
#define ROW_B 784                  // 768 B data + 16 B pad (conflict-free)
#define TILE_B (32 * ROW_B)        // 25088 B per image
#define NTILE 3                    // A0h A1h Bh
#define SMEM_TOTAL (NTILE * TILE_B)   // 75264 B -> 3 CTAs/SM
#define FIN_STRIDE 66
#define FIN_B 8448                 // 32*66*4
#define PART_FLOATS 2048           // 32*32*2
#define OUT_ELEMS (510 * 510 * 2)

// fp16 images: 0:A0h 1:A1h 2:Bh  (row-major [512][768])
__device__ __half g_img[3][512 * HDIM];

union PackH8 { __half h[8]; uint4 v; };

__global__ void prep_kernel(const float* __restrict__ x,
                            const float* __restrict__ W,
                            float* __restrict__ out)
{
    int gid = blockIdx.x * blockDim.x + threadIdx.x;

    // Zero output (atomic adds accumulate); 130050 float4, exact
    if (gid < OUT_ELEMS / 4)
        *(float4*)(out + (size_t)gid * 4) = make_float4(0.f, 0.f, 0.f, 0.f);

    if (gid >= 512 * (HDIM / 8)) return;
    int i  = gid / (HDIM / 8);
    int k0 = (gid % (HDIM / 8)) * 8;

    float4 x0 = *(const float4*)(x + (size_t)i * HDIM + k0);
    float4 x1 = *(const float4*)(x + (size_t)i * HDIM + k0 + 4);
    float4 wa0 = *(const float4*)(W + k0);
    float4 wa1 = *(const float4*)(W + k0 + 4);
    float4 wb0 = *(const float4*)(W + 1536 + k0);
    float4 wb1 = *(const float4*)(W + 1536 + k0 + 4);

    float xs[8] = {x0.x, x0.y, x0.z, x0.w, x1.x, x1.y, x1.z, x1.w};
    float w0[8] = {wa0.x, wa0.y, wa0.z, wa0.w, wa1.x, wa1.y, wa1.z, wa1.w};
    float w1[8] = {wb0.x, wb0.y, wb0.z, wb0.w, wb1.x, wb1.y, wb1.z, wb1.w};

    PackH8 a0, a1, bh;
#pragma unroll
    for (int t = 0; t < 8; t++) {
        a0.h[t] = __float2half_rn(xs[t] * w0[t]);
        a1.h[t] = __float2half_rn(xs[t] * w1[t]);
        bh.h[t] = __float2half_rn(xs[t]);
    }
    size_t off = (size_t)i * HDIM + k0;
    *(uint4*)(&g_img[0][off]) = a0.v;
    *(uint4*)(&g_img[1][off]) = a1.v;
    *(uint4*)(&g_img[2][off]) = bh.v;
}

// ---------------------------------------------------------------------------
__device__ __forceinline__ uint32_t smem_u32(const void* p) {
    uint32_t a;
    asm("{ .reg .u64 t; cvta.to.shared.u64 t, %1; cvt.u32.u64 %0, t; }"
        : "=r"(a) : "l"(p));
    return a;
}

__device__ __forceinline__ void cp16(uint32_t dst, const void* src) {
    asm volatile("cp.async.cg.shared.global [%0], [%1], 16;"
                 :: "r"(dst), "l"(src) : "memory");
}

__device__ __forceinline__ void ldsm4(uint32_t* r, uint32_t addr) {
    asm volatile("ldmatrix.sync.aligned.m8n8.x4.shared.b16 {%0,%1,%2,%3}, [%4];"
                 : "=r"(r[0]), "=r"(r[1]), "=r"(r[2]), "=r"(r[3]) : "r"(addr));
}

__device__ __forceinline__ void mmaf16(float* c, const uint32_t* a,
                                       uint32_t b0, uint32_t b1) {
    asm volatile(
        "mma.sync.aligned.m16n8k16.row.col.f32.f16.f16.f32 "
        "{%0,%1,%2,%3}, {%4,%5,%6,%7}, {%8,%9}, {%0,%1,%2,%3};"
        : "+f"(c[0]), "+f"(c[1]), "+f"(c[2]), "+f"(c[3])
        : "r"(a[0]), "r"(a[1]), "r"(a[2]), "r"(a[3]), "r"(b0), "r"(b1));
}

__device__ __forceinline__ void red_add(float* p, float v) {
    asm volatile("red.global.add.f32 [%0], %1;" :: "l"(p), "f"(v) : "memory");
}

__global__ void __launch_bounds__(512, 3)
pairwise_mma_kernel(const float* __restrict__ bias, float* __restrict__ out)
{
    // Triangular decode: blockIdx.x in [0,136) -> (bi, bj), bj >= bi
    int t = blockIdx.x;
    int bi = 0;
    while (t >= 16 - bi) { t -= 16 - bi; bi++; }
    const int bj = bi + t;
    const int ks = blockIdx.y;        // K split (0/1)

    extern __shared__ __align__(16) char smem[];
    const uint32_t sbase = smem_u32(smem);

    const int tid  = threadIdx.x;
    const int grp  = tid >> 7;        // K-subgroup 0..3 (96 cols each)
    const int gtid = tid & 127;
    const int wid  = gtid >> 5;
    const int lane = tid & 31;
    const int wm = wid >> 1;
    const int wn = wid & 1;

    // ---- bulk cp.async: 3 images x 32 rows x 768 B (this CTA's K-half) ----
    {
        const __half* s0 = &g_img[0][(size_t)(bi * 32) * HDIM + ks * KH];
        const __half* s1 = &g_img[1][(size_t)(bi * 32) * HDIM + ks * KH];
        const __half* s2 = &g_img[2][(size_t)(bj * 32) * HDIM + ks * KH];
        const __half* srcs[3] = {s0, s1, s2};
        // per image: 32 rows x 48 x 16B = 1536 cp; 512 thr -> 3 each
#pragma unroll
        for (int q = 0; q < 3; q++) {
#pragma unroll
            for (int p = 0; p < 3; p++) {
                const int id  = tid + p * 512;      // 0..1535
                const int row = id / 48;
                const int c   = id % 48;
                cp16(sbase + q * TILE_B + row * ROW_B + c * 16,
                     srcs[q] + (size_t)row * HDIM + c * 8);
            }
        }
    }
    asm volatile("cp.async.commit_group;" ::: "memory");
    asm volatile("cp.async.wait_group 0;" ::: "memory");
    __syncthreads();

    // ---- barrier-free LDSM + HMMA: group covers cols [grp*96, grp*96+96) ----
    float acc0[2][4] = {};
    float acc1[2][4] = {};

    const uint32_t arow = sbase + (uint32_t)(wm * 16 + (lane & 15)) * ROW_B
                        + ((lane >> 4) << 4);
    const uint32_t brow = sbase + (uint32_t)(wn * 16 + (lane & 15)) * ROW_B
                        + ((lane >> 4) << 4);
    const uint32_t kb = (uint32_t)(grp * 192);   // 96 cols * 2 B

#pragma unroll
    for (int h = 0; h < 6; h++) {                // 6 k16 slices of K=96
        const uint32_t co = kb + h * 32;
        uint32_t a0[4], a1[4], bh[4];
        ldsm4(a0, 0 * TILE_B + arow + co);
        ldsm4(a1, 1 * TILE_B + arow + co);
        ldsm4(bh, 2 * TILE_B + brow + co);
#pragma unroll
        for (int nf = 0; nf < 2; nf++) {
            mmaf16(acc0[nf], a0, bh[nf], bh[nf + 2]);
            mmaf16(acc1[nf], a1, bh[nf], bh[nf + 2]);
        }
    }

    // ---- combine 4 K-subgroups via smem ----
    __syncthreads();
    float* fin  = (float*)smem;
    float* part = (float*)(smem + FIN_B);

    if (grp != 0) {
        float* pb = part + (grp - 1) * PART_FLOATS;
#pragma unroll
        for (int nf = 0; nf < 2; nf++)
#pragma unroll
            for (int r = 0; r < 4; r++) {
                const int idx = ((gtid * 2 + nf) * 4 + r) * 2;
                pb[idx + 0] = acc0[nf][r];
                pb[idx + 1] = acc1[nf][r];
            }
    }
    __syncthreads();

    if (grp == 0) {
        const float bv0 = bias[0] * 0.5f;   // half bias per K-split
        const float bv1 = bias[1] * 0.5f;
#pragma unroll
        for (int nf = 0; nf < 2; nf++)
#pragma unroll
            for (int r = 0; r < 4; r++) {
                const int idx = ((gtid * 2 + nf) * 4 + r) * 2;
                const float v0 = acc0[nf][r]
                               + part[idx] + part[PART_FLOATS + idx]
                               + part[2 * PART_FLOATS + idx] + bv0;
                const float v1 = acc1[nf][r]
                               + part[idx + 1] + part[PART_FLOATS + idx + 1]
                               + part[2 * PART_FLOATS + idx + 1] + bv1;
                const int ii = wm * 16 + (lane >> 2) + ((r >> 1) << 3);
                const int jj = wn * 16 + nf * 8 + ((lane & 3) << 1) + (r & 1);
                fin[ii * FIN_STRIDE + jj * 2 + 0] = v0;
                fin[ii * FIN_STRIDE + jj * 2 + 1] = v1;
            }
    }
    __syncthreads();

    const int ib = bi * 32;
    const int jb = bj * 32;

    // Direct pass: coalesced red.global.add (2 commutative adds/element total)
    {
        const int ii = tid >> 4;
        const int j0 = (tid & 15) * 2;
        const int gi = ib + ii;
        if (gi >= 1 && gi <= 510) {
            float* orow = out + (size_t)(gi - 1) * 1020;
#pragma unroll
            for (int u = 0; u < 2; u++) {
                const int jj = j0 + u;
                const int gj = jb + jj;
                if (gj >= 1 && gj <= 510) {
                    const float* f = fin + ii * FIN_STRIDE + jj * 2;
                    red_add(orow + (size_t)(gj - 1) * 2 + 0, f[0]);
                    red_add(orow + (size_t)(gj - 1) * 2 + 1, f[1]);
                }
            }
        }
    }
    // Mirror pass (off-diagonal tiles)
    if (bi != bj) {
        const int jj = tid >> 4;
        const int i0 = (tid & 15) * 2;
        const int gj = jb + jj;
        if (gj >= 1 && gj <= 510) {
            float* orow = out + (size_t)(gj - 1) * 1020;
#pragma unroll
            for (int u = 0; u < 2; u++) {
                const int ii = i0 + u;
                const int gi = ib + ii;
                if (gi >= 1 && gi <= 510) {
                    const float* f = fin + ii * FIN_STRIDE + jj * 2;
                    red_add(orow + (size_t)(gi - 1) * 2 + 0, f[0]);
                    red_add(orow + (size_t)(gi - 1) * 2 + 1, f[1]);
                }
            }
        }
    }
}

// ---------------------------------------------------------------------------
extern "C" void kernel_launch(void* const* d_in, const int* in_sizes, int n_in,
                              void* d_out, int out_size)
{
    const float* x = (const float*)d_in[0];   // (1, 512, 768)
    const float* W = (const float*)d_in[1];   // (2, 1536)
    const float* b = (const float*)d_in[2];   // (2,)
    float* out = (float*)d_out;               // (510, 510, 2)

    cudaFuncSetAttribute(pairwise_mma_kernel,
                         cudaFuncAttributeMaxDynamicSharedMemorySize, SMEM_TOTAL);

    // prep + zero: need max(49152 convert, 130050 zero) threads
    prep_kernel<<<(OUT_ELEMS / 4 + 255) / 256, 256>>>(x, W, out);
    pairwise_mma_kernel<<<dim3(136, 2), 512, SMEM_TOTAL>>>(b, out);
}

// round 16
// speedup vs baseline: 1.1572x; 1.1572x over previous
#include <cuda_runtime.h>
#include <cuda_fp16.h>
#include <cstdint>

// out[i,j,o] = sum_h x[i+1,h]*x[j+1,h]*W[o,h] + b[o]
// (diff/W2 term is antisymmetric -> cancels under (P+P^T)/2 symmetrization)
//
// D_o = A_o B^T, A_o = X .* w_o, B = X (512x768 f32)
// Single fp16 MMA per k16: a*b ~= fp16(a)*fp16(b), fp32 accumulate
// (measured rel_err 2.9e-4 < 1e-3).
// prep: 3 fp16 images (A0h=x*w0, A1h=x*w1, Bh=x).
// main (R12 structure): 136 tri-tile CTAs, full K=768 resident in smem
// (3 images, 147 KB) loaded as 2 bulk cp.async mega-chunks, barrier-free
// LDSM+HMMA (4 K-groups x 4 warps), smem combine, coalesced STG + mirror.

#define HDIM 768
#define KM 384                     // K per mega-chunk (2 chunks)
#define ROW_B 784                  // 768 B data + 16 B pad (conflict-free)
#define TILE_B (32 * ROW_B)        // 25088 B per image per chunk
#define NTILE 3                    // A0h A1h Bh
#define STAGE_B (NTILE * TILE_B)   // 75264 B
#define SMEM_TOTAL (2 * STAGE_B)   // 150528 B (1 CTA/SM)
#define KG 96                      // K per group within a mega-chunk
#define FIN_STRIDE 66
#define FIN_B 8448                 // 32*66*4
#define PART_FLOATS 2048           // 32*32*2

// fp16 images: 0:A0h 1:A1h 2:Bh  (row-major [512][768])
__device__ __half g_img[3][512 * HDIM];

union PackH8 { __half h[8]; uint4 v; };

__global__ void prep_kernel(const float* __restrict__ x,
                            const float* __restrict__ W)
{
    int gid = blockIdx.x * blockDim.x + threadIdx.x;
    if (gid >= 512 * (HDIM / 8)) return;
    int i  = gid / (HDIM / 8);
    int k0 = (gid % (HDIM / 8)) * 8;

    float4 x0 = *(const float4*)(x + (size_t)i * HDIM + k0);
    float4 x1 = *(const float4*)(x + (size_t)i * HDIM + k0 + 4);
    float4 wa0 = *(const float4*)(W + k0);
    float4 wa1 = *(const float4*)(W + k0 + 4);
    float4 wb0 = *(const float4*)(W + 1536 + k0);
    float4 wb1 = *(const float4*)(W + 1536 + k0 + 4);

    float xs[8] = {x0.x, x0.y, x0.z, x0.w, x1.x, x1.y, x1.z, x1.w};
    float w0[8] = {wa0.x, wa0.y, wa0.z, wa0.w, wa1.x, wa1.y, wa1.z, wa1.w};
    float w1[8] = {wb0.x, wb0.y, wb0.z, wb0.w, wb1.x, wb1.y, wb1.z, wb1.w};

    PackH8 a0, a1, bh;
#pragma unroll
    for (int t = 0; t < 8; t++) {
        a0.h[t] = __float2half_rn(xs[t] * w0[t]);
        a1.h[t] = __float2half_rn(xs[t] * w1[t]);
        bh.h[t] = __float2half_rn(xs[t]);
    }
    size_t off = (size_t)i * HDIM + k0;
    *(uint4*)(&g_img[0][off]) = a0.v;
    *(uint4*)(&g_img[1][off]) = a1.v;
    *(uint4*)(&g_img[2][off]) = bh.v;
}

// ---------------------------------------------------------------------------
__device__ __forceinline__ uint32_t smem_u32(const void* p) {
    uint32_t a;
    asm("{ .reg .u64 t; cvta.to.shared.u64 t, %1; cvt.u32.u64 %0, t; }"
        : "=r"(a) : "l"(p));
    return a;
}

__device__ __forceinline__ void cp16(uint32_t dst, const void* src) {
    asm volatile("cp.async.cg.shared.global [%0], [%1], 16;"
                 :: "r"(dst), "l"(src) : "memory");
}

__device__ __forceinline__ void ldsm4(uint32_t* r, uint32_t addr) {
    asm volatile("ldmatrix.sync.aligned.m8n8.x4.shared.b16 {%0,%1,%2,%3}, [%4];"
                 : "=r"(r[0]), "=r"(r[1]), "=r"(r[2]), "=r"(r[3]) : "r"(addr));
}

__device__ __forceinline__ void mmaf16(float* c, const uint32_t* a,
                                       uint32_t b0, uint32_t b1) {
    asm volatile(
        "mma.sync.aligned.m16n8k16.row.col.f32.f16.f16.f32 "
        "{%0,%1,%2,%3}, {%4,%5,%6,%7}, {%8,%9}, {%0,%1,%2,%3};"
        : "+f"(c[0]), "+f"(c[1]), "+f"(c[2]), "+f"(c[3])
        : "r"(a[0]), "r"(a[1]), "r"(a[2]), "r"(a[3]), "r"(b0), "r"(b1));
}

__global__ void __launch_bounds__(512, 1)
pairwise_mma_kernel(const float* __restrict__ bias, float* __restrict__ out)
{
    // Triangular decode: blockIdx.x in [0,136) -> (bi, bj), bj >= bi
    int t = blockIdx.x;
    int bi = 0;
    while (t >= 16 - bi) { t -= 16 - bi; bi++; }
    const int bj = bi + t;

    extern __shared__ __align__(16) char smem[];
    const uint32_t sbase = smem_u32(smem);

    const int tid  = threadIdx.x;
    const int grp  = tid >> 7;        // K-group 0..3
    const int gtid = tid & 127;
    const int wid  = gtid >> 5;
    const int lane = tid & 31;
    const int wm = wid >> 1;          // warp row (0..1) of 16
    const int wn = wid & 1;           // warp col (0..1) of 16

    const __half* src[NTILE];
    src[0] = &g_img[0][(size_t)(bi * 32) * HDIM];
    src[1] = &g_img[1][(size_t)(bi * 32) * HDIM];
    src[2] = &g_img[2][(size_t)(bj * 32) * HDIM];

    // ---- bulk load: whole-CTA cooperative, 2 mega-chunks of K=384 ----
    // Per image per chunk: 32 rows x 48 x 16B = 1536 cp; 512 thr -> 3 each.
    auto issue = [&](int st) {
        const uint32_t stb = sbase + st * STAGE_B;
#pragma unroll
        for (int q = 0; q < NTILE; q++) {
#pragma unroll
            for (int p = 0; p < 3; p++) {
                const int id  = tid + p * 512;      // 0..1535
                const int row = id / 48;
                const int c   = id % 48;
                cp16(stb + q * TILE_B + row * ROW_B + c * 16,
                     src[q] + (size_t)row * HDIM + st * KM + c * 8);
            }
        }
    };

    issue(0);
    asm volatile("cp.async.commit_group;" ::: "memory");
    issue(1);
    asm volatile("cp.async.commit_group;" ::: "memory");

    // acc[ch][nf][4]
    float acc0[2][4] = {};
    float acc1[2][4] = {};

    const uint32_t arow = (uint32_t)(wm * 16 + (lane & 15)) * ROW_B
                        + ((lane >> 4) << 4);
    const uint32_t brow = (uint32_t)(wn * 16 + (lane & 15)) * ROW_B
                        + ((lane >> 4) << 4);

    // Barrier-free compute over resident data: group g covers K-cols
    // [g*96, g*96+96) of this mega-chunk = 6 k16 slices.
    auto compute = [&](int st) {
        const uint32_t tb = sbase + st * STAGE_B;
        const uint32_t kb = (uint32_t)(grp * KG * 2);   // byte col base
#pragma unroll
        for (int h = 0; h < 6; h++) {
            const uint32_t co = kb + h * 32;
            uint32_t a0[4], a1[4], bh[4];
            ldsm4(a0, tb + 0 * TILE_B + arow + co);
            ldsm4(a1, tb + 1 * TILE_B + arow + co);
            ldsm4(bh, tb + 2 * TILE_B + brow + co);
#pragma unroll
            for (int nf = 0; nf < 2; nf++) {
                mmaf16(acc0[nf], a0, bh[nf], bh[nf + 2]);
                mmaf16(acc1[nf], a1, bh[nf], bh[nf + 2]);
            }
        }
    };

    asm volatile("cp.async.wait_group 1;" ::: "memory");
    __syncthreads();
    compute(0);                       // overlaps the stage-1 load
    asm volatile("cp.async.wait_group 0;" ::: "memory");
    __syncthreads();
    compute(1);

    // ---- combine 4 K-quarters via smem, then coalesced STG ----
    __syncthreads();
    float* fin  = (float*)smem;
    float* part = (float*)(smem + FIN_B);

    if (grp != 0) {
        float* pb = part + (grp - 1) * PART_FLOATS;
#pragma unroll
        for (int nf = 0; nf < 2; nf++)
#pragma unroll
            for (int r = 0; r < 4; r++) {
                const int idx = ((gtid * 2 + nf) * 4 + r) * 2;
                pb[idx + 0] = acc0[nf][r];
                pb[idx + 1] = acc1[nf][r];
            }
    }
    __syncthreads();

    if (grp == 0) {
        const float bv0 = bias[0];
        const float bv1 = bias[1];
#pragma unroll
        for (int nf = 0; nf < 2; nf++)
#pragma unroll
            for (int r = 0; r < 4; r++) {
                const int idx = ((gtid * 2 + nf) * 4 + r) * 2;
                const float v0 = acc0[nf][r]
                               + part[idx] + part[PART_FLOATS + idx]
                               + part[2 * PART_FLOATS + idx] + bv0;
                const float v1 = acc1[nf][r]
                               + part[idx + 1] + part[PART_FLOATS + idx + 1]
                               + part[2 * PART_FLOATS + idx + 1] + bv1;
                const int ii = wm * 16 + (lane >> 2) + ((r >> 1) << 3);
                const int jj = wn * 16 + nf * 8 + ((lane & 3) << 1) + (r & 1);
                fin[ii * FIN_STRIDE + jj * 2 + 0] = v0;
                fin[ii * FIN_STRIDE + jj * 2 + 1] = v1;
            }
    }
    __syncthreads();

    const int ib = bi * 32;
    const int jb = bj * 32;

    // Direct pass: 512 threads, each 2 cols of one row (contiguous float2)
    {
        const int ii = tid >> 4;
        const int j0 = (tid & 15) * 2;
        const int gi = ib + ii;
        if (gi >= 1 && gi <= 510) {
            float* orow = out + (size_t)(gi - 1) * 1020;
#pragma unroll
            for (int u = 0; u < 2; u++) {
                const int jj = j0 + u;
                const int gj = jb + jj;
                if (gj >= 1 && gj <= 510) {
                    float2 v = *(float2*)(fin + ii * FIN_STRIDE + jj * 2);
                    *(float2*)(orow + (size_t)(gj - 1) * 2) = v;
                }
            }
        }
    }
    // Mirror pass (off-diagonal tiles)
    if (bi != bj) {
        const int jj = tid >> 4;
        const int i0 = (tid & 15) * 2;
        const int gj = jb + jj;
        if (gj >= 1 && gj <= 510) {
            float* orow = out + (size_t)(gj - 1) * 1020;
#pragma unroll
            for (int u = 0; u < 2; u++) {
                const int ii = i0 + u;
                const int gi = ib + ii;
                if (gi >= 1 && gi <= 510) {
                    float2 v = *(float2*)(fin + ii * FIN_STRIDE + jj * 2);
                    *(float2*)(orow + (size_t)(gi - 1) * 2) = v;
                }
            }
        }
    }
}

// ---------------------------------------------------------------------------
extern "C" void kernel_launch(void* const* d_in, const int* in_sizes, int n_in,
                              void* d_out, int out_size)
{
    const float* x = (const float*)d_in[0];   // (1, 512, 768)
    const float* W = (const float*)d_in[1];   // (2, 1536)
    const float* b = (const float*)d_in[2];   // (2,)
    float* out = (float*)d_out;               // (510, 510, 2)

    cudaFuncSetAttribute(pairwise_mma_kernel,
                         cudaFuncAttributeMaxDynamicSharedMemorySize, SMEM_TOTAL);

    prep_kernel<<<192, 256>>>(x, W);
    pairwise_mma_kernel<<<136, 512, SMEM_TOTAL>>>(b, out);
}

// round 17
// speedup vs baseline: 1.1805x; 1.0201x over previous
#include <cuda_runtime.h>
#include <cuda_fp16.h>
#include <cstdint>

// out[i,j,o] = sum_h x[i+1,h]*x[j+1,h]*W[o,h] + b[o]
// (diff/W2 term is antisymmetric -> cancels under (P+P^T)/2 symmetrization)
//
// D_o = A_o B^T, A_o = X .* w_o, B = X (512x768 f32)
// Single fp16 MMA per k16 (measured rel_err 2.9e-4 < 1e-3).
//
// SINGLE kernel, 136 co-resident CTAs (<=148 SMs, wave-1 guaranteed):
//  Phase 0: grid cooperatively converts x -> 3 fp16 images (each of the
//           49152 8-col chunks converted exactly ONCE), then a global
//           spin barrier (self-resetting across graph replays).
//  Phase 1: bulk cp.async of full K=768 (3 images, 147 KB) in 2 chunks.
//  Phase 2: barrier-free LDSM + 1-term fp16 HMMA (4 K-groups x 4 warps).
//  Phase 3: smem combine + coalesced STG, upper-tri tiles + mirror.

#define HDIM 768
#define KM 384                     // K per mega-chunk (2 chunks)
#define ROW_B 784                  // 768 B data + 16 B pad (conflict-free)
#define TILE_B (32 * ROW_B)        // 25088 B per image per chunk
#define NTILE 3                    // A0h A1h Bh
#define STAGE_B (NTILE * TILE_B)   // 75264 B
#define SMEM_TOTAL (2 * STAGE_B)   // 150528 B (1 CTA/SM)
#define KG 96                      // K per group within a mega-chunk
#define FIN_STRIDE 66
#define FIN_B 8448                 // 32*66*4
#define PART_FLOATS 2048           // 32*32*2
#define NCTA 136

// fp16 images: 0:A0h 1:A1h 2:Bh  (row-major [512][768])
__device__ __half g_img[3][512 * HDIM];
// Grid barrier state (self-resetting; zero-initialized at module load)
__device__ int g_arrive = 0;
__device__ int g_depart = 0;

union PackH8 { __half h[8]; uint4 v; };

__device__ __forceinline__ uint32_t smem_u32(const void* p) {
    uint32_t a;
    asm("{ .reg .u64 t; cvta.to.shared.u64 t, %1; cvt.u32.u64 %0, t; }"
        : "=r"(a) : "l"(p));
    return a;
}

__device__ __forceinline__ void cp16(uint32_t dst, const void* src) {
    asm volatile("cp.async.cg.shared.global [%0], [%1], 16;"
                 :: "r"(dst), "l"(src) : "memory");
}

__device__ __forceinline__ void ldsm4(uint32_t* r, uint32_t addr) {
    asm volatile("ldmatrix.sync.aligned.m8n8.x4.shared.b16 {%0,%1,%2,%3}, [%4];"
                 : "=r"(r[0]), "=r"(r[1]), "=r"(r[2]), "=r"(r[3]) : "r"(addr));
}

__device__ __forceinline__ void mmaf16(float* c, const uint32_t* a,
                                       uint32_t b0, uint32_t b1) {
    asm volatile(
        "mma.sync.aligned.m16n8k16.row.col.f32.f16.f16.f32 "
        "{%0,%1,%2,%3}, {%4,%5,%6,%7}, {%8,%9}, {%0,%1,%2,%3};"
        : "+f"(c[0]), "+f"(c[1]), "+f"(c[2]), "+f"(c[3])
        : "r"(a[0]), "r"(a[1]), "r"(a[2]), "r"(a[3]), "r"(b0), "r"(b1));
}

__global__ void __launch_bounds__(512, 1)
pairwise_fused_kernel(const float* __restrict__ x, const float* __restrict__ W,
                      const float* __restrict__ bias, float* __restrict__ out)
{
    // Triangular decode: blockIdx.x in [0,136) -> (bi, bj), bj >= bi
    int t = blockIdx.x;
    int bi = 0;
    while (t >= 16 - bi) { t -= 16 - bi; bi++; }
    const int bj = bi + t;

    extern __shared__ __align__(16) char smem[];
    const uint32_t sbase = smem_u32(smem);

    const int tid  = threadIdx.x;
    const int grp  = tid >> 7;        // K-group 0..3
    const int gtid = tid & 127;
    const int wid  = gtid >> 5;
    const int lane = tid & 31;
    const int wm = wid >> 1;          // warp row (0..1) of 16
    const int wn = wid & 1;           // warp col (0..1) of 16

    // ---- Phase 0: cooperative convert (each chunk exactly once) ----
    // 512 rows x 96 chunks = 49152 items = CTAs 0..95 x 512 threads.
    {
        const int gid = blockIdx.x * 512 + tid;
        if (gid < 512 * (HDIM / 8)) {
            const int i  = gid / (HDIM / 8);
            const int k0 = (gid % (HDIM / 8)) * 8;

            float4 x0 = *(const float4*)(x + (size_t)i * HDIM + k0);
            float4 x1 = *(const float4*)(x + (size_t)i * HDIM + k0 + 4);
            float4 wa0 = *(const float4*)(W + k0);
            float4 wa1 = *(const float4*)(W + k0 + 4);
            float4 wb0 = *(const float4*)(W + 1536 + k0);
            float4 wb1 = *(const float4*)(W + 1536 + k0 + 4);

            float xs[8] = {x0.x, x0.y, x0.z, x0.w, x1.x, x1.y, x1.z, x1.w};
            float w0[8] = {wa0.x, wa0.y, wa0.z, wa0.w, wa1.x, wa1.y, wa1.z, wa1.w};
            float w1[8] = {wb0.x, wb0.y, wb0.z, wb0.w, wb1.x, wb1.y, wb1.z, wb1.w};

            PackH8 a0, a1, bh;
#pragma unroll
            for (int u = 0; u < 8; u++) {
                a0.h[u] = __float2half_rn(xs[u] * w0[u]);
                a1.h[u] = __float2half_rn(xs[u] * w1[u]);
                bh.h[u] = __float2half_rn(xs[u]);
            }
            size_t off = (size_t)i * HDIM + k0;
            *(uint4*)(&g_img[0][off]) = a0.v;
            *(uint4*)(&g_img[1][off]) = a1.v;
            *(uint4*)(&g_img[2][off]) = bh.v;
        }
        __threadfence();              // image writes visible grid-wide
        __syncthreads();              // whole CTA done converting

        if (tid == 0) {
            atomicAdd(&g_arrive, 1);
            while (atomicAdd(&g_arrive, 0) < NCTA)
                __nanosleep(64);
            // Self-reset: ticket2==NCTA-1 implies every CTA has already
            // exited the spin above, so zeroing is race-free.
            int t2 = atomicAdd(&g_depart, 1);
            if (t2 == NCTA - 1) {
                atomicExch(&g_arrive, 0);
                atomicExch(&g_depart, 0);
            }
        }
        __syncthreads();              // release all threads of the CTA
    }

    const __half* src[NTILE];
    src[0] = &g_img[0][(size_t)(bi * 32) * HDIM];
    src[1] = &g_img[1][(size_t)(bi * 32) * HDIM];
    src[2] = &g_img[2][(size_t)(bj * 32) * HDIM];

    // ---- Phase 1: bulk load, 2 mega-chunks of K=384 ----
    auto issue = [&](int st) {
        const uint32_t stb = sbase + st * STAGE_B;
#pragma unroll
        for (int q = 0; q < NTILE; q++) {
#pragma unroll
            for (int p = 0; p < 3; p++) {
                const int id  = tid + p * 512;      // 0..1535
                const int row = id / 48;
                const int c   = id % 48;
                cp16(stb + q * TILE_B + row * ROW_B + c * 16,
                     src[q] + (size_t)row * HDIM + st * KM + c * 8);
            }
        }
    };

    issue(0);
    asm volatile("cp.async.commit_group;" ::: "memory");
    issue(1);
    asm volatile("cp.async.commit_group;" ::: "memory");

    // ---- Phase 2: barrier-free LDSM + HMMA ----
    float acc0[2][4] = {};
    float acc1[2][4] = {};

    const uint32_t arow = (uint32_t)(wm * 16 + (lane & 15)) * ROW_B
                        + ((lane >> 4) << 4);
    const uint32_t brow = (uint32_t)(wn * 16 + (lane & 15)) * ROW_B
                        + ((lane >> 4) << 4);

    auto compute = [&](int st) {
        const uint32_t tb = sbase + st * STAGE_B;
        const uint32_t kb = (uint32_t)(grp * KG * 2);
#pragma unroll
        for (int h = 0; h < 6; h++) {
            const uint32_t co = kb + h * 32;
            uint32_t a0[4], a1[4], bh[4];
            ldsm4(a0, tb + 0 * TILE_B + arow + co);
            ldsm4(a1, tb + 1 * TILE_B + arow + co);
            ldsm4(bh, tb + 2 * TILE_B + brow + co);
#pragma unroll
            for (int nf = 0; nf < 2; nf++) {
                mmaf16(acc0[nf], a0, bh[nf], bh[nf + 2]);
                mmaf16(acc1[nf], a1, bh[nf], bh[nf + 2]);
            }
        }
    };

    asm volatile("cp.async.wait_group 1;" ::: "memory");
    __syncthreads();
    compute(0);                       // overlaps the stage-1 load
    asm volatile("cp.async.wait_group 0;" ::: "memory");
    __syncthreads();
    compute(1);

    // ---- Phase 3: combine 4 K-quarters via smem, then coalesced STG ----
    __syncthreads();
    float* fin  = (float*)smem;
    float* part = (float*)(smem + FIN_B);

    if (grp != 0) {
        float* pb = part + (grp - 1) * PART_FLOATS;
#pragma unroll
        for (int nf = 0; nf < 2; nf++)
#pragma unroll
            for (int r = 0; r < 4; r++) {
                const int idx = ((gtid * 2 + nf) * 4 + r) * 2;
                pb[idx + 0] = acc0[nf][r];
                pb[idx + 1] = acc1[nf][r];
            }
    }
    __syncthreads();

    if (grp == 0) {
        const float bv0 = bias[0];
        const float bv1 = bias[1];
#pragma unroll
        for (int nf = 0; nf < 2; nf++)
#pragma unroll
            for (int r = 0; r < 4; r++) {
                const int idx = ((gtid * 2 + nf) * 4 + r) * 2;
                const float v0 = acc0[nf][r]
                               + part[idx] + part[PART_FLOATS + idx]
                               + part[2 * PART_FLOATS + idx] + bv0;
                const float v1 = acc1[nf][r]
                               + part[idx + 1] + part[PART_FLOATS + idx + 1]
                               + part[2 * PART_FLOATS + idx + 1] + bv1;
                const int ii = wm * 16 + (lane >> 2) + ((r >> 1) << 3);
                const int jj = wn * 16 + nf * 8 + ((lane & 3) << 1) + (r & 1);
                fin[ii * FIN_STRIDE + jj * 2 + 0] = v0;
                fin[ii * FIN_STRIDE + jj * 2 + 1] = v1;
            }
    }
    __syncthreads();

    const int ib = bi * 32;
    const int jb = bj * 32;

    // Direct pass: 512 threads, each 2 cols of one row (contiguous float2)
    {
        const int ii = tid >> 4;
        const int j0 = (tid & 15) * 2;
        const int gi = ib + ii;
        if (gi >= 1 && gi <= 510) {
            float* orow = out + (size_t)(gi - 1) * 1020;
#pragma unroll
            for (int u = 0; u < 2; u++) {
                const int jj = j0 + u;
                const int gj = jb + jj;
                if (gj >= 1 && gj <= 510) {
                    float2 v = *(float2*)(fin + ii * FIN_STRIDE + jj * 2);
                    *(float2*)(orow + (size_t)(gj - 1) * 2) = v;
                }
            }
        }
    }
    // Mirror pass (off-diagonal tiles)
    if (bi != bj) {
        const int jj = tid >> 4;
        const int i0 = (tid & 15) * 2;
        const int gj = jb + jj;
        if (gj >= 1 && gj <= 510) {
            float* orow = out + (size_t)(gj - 1) * 1020;
#pragma unroll
            for (int u = 0; u < 2; u++) {
                const int ii = i0 + u;
                const int gi = ib + ii;
                if (gi >= 1 && gi <= 510) {
                    float2 v = *(float2*)(fin + ii * FIN_STRIDE + jj * 2);
                    *(float2*)(orow + (size_t)(gi - 1) * 2) = v;
                }
            }
        }
    }
}

// ---------------------------------------------------------------------------
extern "C" void kernel_launch(void* const* d_in, const int* in_sizes, int n_in,
                              void* d_out, int out_size)
{
    const float* x = (const float*)d_in[0];   // (1, 512, 768)
    const float* W = (const float*)d_in[1];   // (2, 1536)
    const float* b = (const float*)d_in[2];   // (2,)
    float* out = (float*)d_out;               // (510, 510, 2)

    cudaFuncSetAttribute(pairwise_fused_kernel,
                         cudaFuncAttributeMaxDynamicSharedMemorySize, SMEM_TOTAL);

    pairwise_fused_kernel<<<NCTA, 512, SMEM_TOTAL>>>(x, W, b, out);
}